// round 16
// baseline (speedup 1.0000x reference)
#include <cuda_runtime.h>

#define NB   32    // batch
#define PM    4    // probe modes
#define NSL   8    // slices
#define NN  256    // ROI
#define LNS  16    // lines per block
#define LNSR  8    // lines per block for k_row (128 thr)

typedef unsigned long long u64;  // packed complex: lo=re, hi=im (f32x2)

// psi[b][pm][y][x]; state between kernels is Fr(psi) (row-FFT'd, natural order)
__device__ u64 g_psi[NB * PM * NN * NN];
// Hs[row][col] = H[row][col] / 256 (row-major, packed)
__device__ u64 g_Hs[NN * NN];

// 4x4 index transpose (involution): P4(P4(m)) == m
__host__ __device__ constexpr int P4(int m) { return ((m & 3) << 2) | (m >> 2); }

// ---- packed f32x2 complex primitives (sm_100a) ------------------------------
__device__ __forceinline__ u64 c_pack(float x, float y) {
    u64 r; asm("mov.b64 %0, {%1, %2};" : "=l"(r) : "f"(x), "f"(y)); return r;
}
__device__ __forceinline__ float2 c_unpack(u64 a) {
    float2 r; asm("mov.b64 {%0, %1}, %2;" : "=f"(r.x), "=f"(r.y) : "l"(a)); return r;
}
__device__ __forceinline__ u64 c_add(u64 a, u64 b) {
    u64 r; asm("add.rn.f32x2 %0, %1, %2;" : "=l"(r) : "l"(a), "l"(b)); return r;
}
__device__ __forceinline__ u64 c_sub(u64 a, u64 b) {
    u64 r; asm("sub.rn.f32x2 %0, %1, %2;" : "=l"(r) : "l"(a), "l"(b)); return r;
}
__device__ __forceinline__ u64 c_mi(u64 a) {
    float2 v = c_unpack(a);
    return c_pack(v.y, -v.x);
}
__device__ __forceinline__ u64 cmul_u(u64 a, u64 b) {
    float2 A = c_unpack(a), B = c_unpack(b);
    return c_pack(fmaf(A.x, B.x, -A.y * B.y), fmaf(A.x, B.y, A.y * B.x));
}
template <bool INV>
__device__ __forceinline__ u64 twmul(u64 a, float2 w) {
    float2 A = c_unpack(a);
    float wy = INV ? -w.y : w.y;
    return c_pack(fmaf(A.x, w.x, -A.y * wy), fmaf(A.x, wy, A.y * w.x));
}
__device__ __forceinline__ float2 cmul(float2 a, float2 b) {
    return make_float2(fmaf(a.x, b.x, -a.y * b.y), fmaf(a.x, b.y, a.y * b.x));
}

// W16^m = exp(-2*pi*i*m/16)
__constant__ float2 W16C[10] = {
    { 1.0f,          0.0f        },
    { 0.92387953f,  -0.38268343f },
    { 0.70710678f,  -0.70710678f },
    { 0.38268343f,  -0.92387953f },
    { 0.0f,         -1.0f        },
    {-0.38268343f,  -0.92387953f },
    {-0.70710678f,  -0.70710678f },
    {-0.92387953f,  -0.38268343f },
    {-1.0f,          0.0f        },
    {-0.92387953f,   0.38268343f },
};

template <bool INV>
__device__ __forceinline__ void bf4p(u64& a, u64& b, u64& c, u64& d) {
    u64 t0 = c_add(a, c), t1 = c_sub(a, c);
    u64 t2 = c_add(b, d), t3 = c_sub(b, d);
    a = c_add(t0, t2);
    c = c_sub(t0, t2);
    u64 m = c_mi(t3);
    if (!INV) { b = c_add(t1, m); d = c_sub(t1, m); }
    else      { b = c_sub(t1, m); d = c_add(t1, m); }
}

// In-place 16-point DFT through a compile-time physical map φ = (PIN ? P4 : id).
// Input x[n] at v[φ(n)]; output X[m] lands at v[φ(P4(m))] — i.e. PIN=false:
// natural in → P4-permuted out; PIN=true: P4-permuted in → natural out.
// No output array, no permutation copies.
template <bool INV, bool PIN>
__device__ __forceinline__ void fft16ip(u64* v) {
#define PHI(i) (PIN ? P4(i) : (i))
#pragma unroll
    for (int n2 = 0; n2 < 4; n2++)
        bf4p<INV>(v[PHI(n2)], v[PHI(4 + n2)], v[PHI(8 + n2)], v[PHI(12 + n2)]);
#pragma unroll
    for (int k1 = 1; k1 < 4; k1++)
#pragma unroll
        for (int n2 = 1; n2 < 4; n2++)
            v[PHI(4 * k1 + n2)] = twmul<INV>(v[PHI(4 * k1 + n2)], W16C[k1 * n2]);
#pragma unroll
    for (int k1 = 0; k1 < 4; k1++)
        bf4p<INV>(v[PHI(4 * k1 + 0)], v[PHI(4 * k1 + 1)],
                  v[PHI(4 * k1 + 2)], v[PHI(4 * k1 + 3)]);
#undef PHI
}

// tw[k-1] = W256^{j*k}, k=1..15, log-depth product tree.
__device__ __forceinline__ void make_tw256(float2* tw, int j) {
    float s, c;
    sincospif(-(float)j * (1.0f / 128.0f), &s, &c);
    float2 w1 = make_float2(c, s);
    float2 w2 = cmul(w1, w1);
    float2 w3 = cmul(w1, w2);
    float2 w4 = cmul(w2, w2);
    float2 w5 = cmul(w1, w4);
    float2 w6 = cmul(w2, w4);
    float2 w7 = cmul(w3, w4);
    float2 w8 = cmul(w4, w4);
    tw[0] = w1;  tw[1] = w2;  tw[2] = w3;  tw[3] = w4;
    tw[4] = w5;  tw[5] = w6;  tw[6] = w7;  tw[7] = w8;
    tw[8]  = cmul(w1, w8);
    tw[9]  = cmul(w2, w8);
    tw[10] = cmul(w3, w8);
    tw[11] = cmul(w4, w8);
    tw[12] = cmul(w5, w8);
    tw[13] = cmul(w6, w8);
    tw[14] = cmul(w7, w8);
}

// Warp-local 256-pt FFT (16 threads/line in one warp), in-place, permutation-
// folded. PIN: input is P4-permuted (element 16n+t at reg[P4(n)]); else natural.
// POUTP: leave output P4-permuted (element 16k+t at reg[P4(k)]); else natural.
template <bool INV, bool PIN, bool POUTP>
__device__ __forceinline__ void fft256ip(u64 reg[16], int t, u64* tr,
                                         const float2* tw) {
    fft16ip<INV, PIN>(reg);
    // X1[k1] now at reg[q(k1)], q = PIN ? id : P4
#define Q(i) (PIN ? (i) : P4(i))
#pragma unroll
    for (int k1 = 1; k1 < 16; k1++)
        reg[Q(k1)] = twmul<INV>(reg[Q(k1)], tw[k1 - 1]);
#pragma unroll
    for (int k1 = 0; k1 < 16; k1++) tr[k1 * 17 + t] = reg[Q(k1)];
#undef Q
    __syncwarp();
    if (POUTP) {
#pragma unroll
        for (int n2 = 0; n2 < 16; n2++) reg[n2] = tr[t * 17 + n2];
        __syncwarp();
        fft16ip<INV, false>(reg);   // out at P4
    } else {
#pragma unroll
        for (int n2 = 0; n2 < 16; n2++) reg[P4(n2)] = tr[t * 17 + n2];
        __syncwarp();
        fft16ip<INV, true>(reg);    // out natural
    }
}

// Cross-warp 256-pt FFT (thread owns a column; j spans warps), same folding.
template <bool INV, bool PIN, bool POUTP>
__device__ __forceinline__ void fft256blkip(u64 reg[16], int j, int ln, u64* W,
                                            const float2* tw) {
    fft16ip<INV, PIN>(reg);
#define Q(i) (PIN ? (i) : P4(i))
#pragma unroll
    for (int k1 = 1; k1 < 16; k1++)
        reg[Q(k1)] = twmul<INV>(reg[Q(k1)], tw[k1 - 1]);
#pragma unroll
    for (int k1 = 0; k1 < 16; k1++) W[(k1 * 17 + j) * 16 + ln] = reg[Q(k1)];
#undef Q
    __syncthreads();
    if (POUTP) {
#pragma unroll
        for (int n2 = 0; n2 < 16; n2++) reg[n2] = W[(j * 17 + n2) * 16 + ln];
        __syncthreads();
        fft16ip<INV, false>(reg);
    } else {
#pragma unroll
        for (int n2 = 0; n2 < 16; n2++) reg[P4(n2)] = W[(j * 17 + n2) * 16 + ln];
        __syncthreads();
        fft16ip<INV, true>(reg);
    }
}

// ---------------------------------------------------------------------------
__global__ void k_prep(const float* __restrict__ Hr, const float* __restrict__ Hi) {
    int i = blockIdx.x * blockDim.x + threadIdx.x;
    g_Hs[i] = c_pack(Hr[i] * (1.0f / 256.0f), Hi[i] * (1.0f / 256.0f));
}

// ---------------------------------------------------------------------------
// k_init: psi = probe_translated * obj0, then forward row FFT (natural out).
// ---------------------------------------------------------------------------
__global__ __launch_bounds__(256, 2) void k_init(
    const float* __restrict__ obj, const float* __restrict__ probe,
    const float* __restrict__ shifts, const int* __restrict__ crop,
    const int* __restrict__ idxs) {
    __shared__ u64 buf[LNS * 272];
    int t = threadIdx.x, ly = threadIdx.y;
    int img = blockIdx.y;
    int b = img >> 2, pm = img & 3;
    int r = blockIdx.x * LNS + ly;

    int id = idxs[b];
    float tH = shifts[2 * id + 0];
    float tW = shifts[2 * id + 1];
    int p0 = crop[2 * id + 0];
    int p1 = crop[2 * id + 1];

    float ys = (float)r - tH;
    float y0f = floorf(ys);
    float wy = ys - y0f;
    int y0 = (int)y0f;

    u64 reg[16];
#pragma unroll
    for (int jj = 0; jj < 16; jj++) {
        int c = 16 * jj + t;
        float xs = (float)c - tW;
        float x0f = floorf(xs);
        float wx = xs - x0f;
        int x0 = (int)x0f;

        float amp = 0.f, ph = 0.f;
#pragma unroll
        for (int dy = 0; dy < 2; dy++) {
            int yy = y0 + dy;
            float wyt = dy ? wy : (1.f - wy);
            if (yy >= 0 && yy < NN) {
#pragma unroll
                for (int dx = 0; dx < 2; dx++) {
                    int xx = x0 + dx;
                    float w = wyt * (dx ? wx : (1.f - wx));
                    if (xx >= 0 && xx < NN) {
                        float2 v = *(const float2*)(probe +
                            ((size_t)(pm * NN + yy) * NN + xx) * 2);
                        amp = fmaf(w, v.x, amp);
                        ph  = fmaf(w, v.y, ph);
                    }
                }
            }
        }
        float sn, cs;
        __sincosf(ph, &sn, &cs);
        float2 pc = make_float2(amp * cs, amp * sn);

        float2 o = *(const float2*)(obj + (((size_t)(p0 + r)) * 1024 + (p1 + c)) * 2);
        float so, co;
        __sincosf(o.y, &so, &co);
        float2 oc = make_float2(o.x * co, o.x * so);
        reg[jj] = c_pack(fmaf(pc.x, oc.x, -pc.y * oc.y),
                         fmaf(pc.x, oc.y,  pc.y * oc.x));
    }

    float2 tw[15];
    make_tw256(tw, t);
    fft256ip<false, false, false>(reg, t, buf + ly * 272, tw);  // natural out

    u64* dst = g_psi + ((size_t)img * NN + r) * NN;
#pragma unroll
    for (int k = 0; k < 16; k++) dst[16 * k + t] = reg[k];
}

// ---------------------------------------------------------------------------
// k_col: per column: Fc -> * (H/256) -> Fc^{-1}. PDL prologue; no staging.
// fwd: natural -> P4; H multiply P4-indexed; inv: P4 -> natural.
// ---------------------------------------------------------------------------
__global__ __launch_bounds__(256, 2) void k_col() {
    __shared__ u64 W[16 * 17 * 16];
    int t = threadIdx.x;   // column within tile (line)
    int j = threadIdx.y;   // intra-line FFT index
    int img = blockIdx.y;
    int cb = blockIdx.x * 16;
    u64* psi = g_psi + (size_t)img * NN * NN;

    float2 tw[15];
    make_tw256(tw, j);      // psi-independent prologue

    cudaGridDependencySynchronize();

    u64 reg[16];
#pragma unroll
    for (int it = 0; it < 16; it++)
        reg[it] = psi[(size_t)(16 * it + j) * NN + cb + t];

    fft256blkip<false, false, true>(reg, j, t, W, tw);   // out at P4

#pragma unroll
    for (int k = 0; k < 16; k++)
        reg[P4(k)] = cmul_u(reg[P4(k)], g_Hs[(size_t)(16 * k + j) * NN + cb + t]);

    fft256blkip<true, true, false>(reg, j, t, W, tw);    // natural out

#pragma unroll
    for (int k = 0; k < 16; k++)
        psi[(size_t)(16 * k + j) * NN + cb + t] = reg[k];
}

// ---------------------------------------------------------------------------
// k_row: per row: Fr^{-1}/256 -> * obj_z -> Fr. 8 lines / 128 threads.
// PDL prologue. inv: natural -> P4; obj multiply P4-indexed; fwd: P4 -> natural.
// ---------------------------------------------------------------------------
__global__ __launch_bounds__(128, 6) void k_row(
    const float* __restrict__ obj, const int* __restrict__ crop,
    const int* __restrict__ idxs, int z) {
    __shared__ u64 buf[LNSR * 272];
    __shared__ u64 sOC[LNSR * 256];
    int t = threadIdx.x, ly = threadIdx.y;
    int b = blockIdx.y;
    int r = blockIdx.x * LNSR + ly;

    int id = idxs[b];
    int p0 = crop[2 * id + 0];
    int p1 = crop[2 * id + 1];
    const float inv = 1.0f / 256.0f;

    u64* oc = sOC + ly * 256;
#pragma unroll
    for (int jj = 0; jj < 16; jj++) {
        int c = 16 * jj + t;
        float2 o = *(const float2*)(obj +
            (((size_t)z * 1024 + p0 + r) * 1024 + (p1 + c)) * 2);
        float so, co;
        __sincosf(o.y, &so, &co);
        oc[c] = c_pack(o.x * co * inv, o.x * so * inv);
    }
    __syncwarp();

    float2 tw[15];
    make_tw256(tw, t);

    cudaGridDependencySynchronize();

    for (int pm = 0; pm < PM; pm++) {
        u64* psi = g_psi + ((size_t)(b * PM + pm) * NN + r) * NN;
        u64 reg[16];
#pragma unroll
        for (int k = 0; k < 16; k++) reg[k] = psi[16 * k + t];

        fft256ip<true, false, true>(reg, t, buf + ly * 272, tw);   // out at P4
#pragma unroll
        for (int jj = 0; jj < 16; jj++)
            reg[P4(jj)] = cmul_u(reg[P4(jj)], oc[16 * jj + t]);
        fft256ip<false, true, false>(reg, t, buf + ly * 272, tw);  // natural out

#pragma unroll
        for (int k = 0; k < 16; k++) psi[16 * k + t] = reg[k];
    }
}

// ---------------------------------------------------------------------------
// k_final: per column: Fc, accumulate |.|^2 over 4 probe modes. PDL prologue.
// ---------------------------------------------------------------------------
__global__ __launch_bounds__(256, 2) void k_final(float* __restrict__ out) {
    __shared__ u64 W[16 * 17 * 16];
    int t = threadIdx.x;
    int j = threadIdx.y;
    int b = blockIdx.y;
    int cb = blockIdx.x * 16;

    float2 tw[15];
    make_tw256(tw, j);

    cudaGridDependencySynchronize();

    float acc[16];
#pragma unroll
    for (int k = 0; k < 16; k++) acc[k] = 0.f;

    for (int pm = 0; pm < PM; pm++) {
        u64* psi = g_psi + (size_t)(b * PM + pm) * NN * NN;
        u64 reg[16];
#pragma unroll
        for (int it = 0; it < 16; it++)
            reg[it] = psi[(size_t)(16 * it + j) * NN + cb + t];

        fft256blkip<false, false, true>(reg, j, t, W, tw);  // out at P4

#pragma unroll
        for (int k = 0; k < 16; k++) {
            float2 v = c_unpack(reg[P4(k)]);   // element 16k+j
            acc[k] = fmaf(v.x, v.x, fmaf(v.y, v.y, acc[k]));
        }
    }

#pragma unroll
    for (int k = 0; k < 16; k++)
        out[(size_t)b * NN * NN + (size_t)(16 * k + j) * NN + cb + t] = acc[k];
}

// ---------------------------------------------------------------------------
extern "C" void kernel_launch(void* const* d_in, const int* in_sizes, int n_in,
                              void* d_out, int out_size) {
    const float* obj    = (const float*)d_in[0];  // (1,8,1024,1024,2)
    const float* probe  = (const float*)d_in[1];  // (4,256,256,2)
    const float* shifts = (const float*)d_in[2];  // (1024,2)
    const int*   crop   = (const int*)d_in[3];    // (1024,2)
    const float* Hr     = (const float*)d_in[4];  // (256,256)
    const float* Hi     = (const float*)d_in[5];  // (256,256)
    const int*   idxs   = (const int*)d_in[6];    // (32,)
    float* out = (float*)d_out;                   // (32,256,256)

    cudaLaunchAttribute pdlAttr[1];
    pdlAttr[0].id = cudaLaunchAttributeProgrammaticStreamSerialization;
    pdlAttr[0].val.programmaticStreamSerializationAllowed = 1;

    k_prep<<<256, 256>>>(Hr, Hi);
    k_init<<<dim3(NN / LNS, NB * PM), dim3(16, LNS)>>>(obj, probe, shifts, crop, idxs);

    cudaLaunchConfig_t cfgCol = {};
    cfgCol.gridDim = dim3(NN / 16, NB * PM);
    cfgCol.blockDim = dim3(16, 16);
    cfgCol.attrs = pdlAttr;
    cfgCol.numAttrs = 1;

    cudaLaunchConfig_t cfgRow = {};
    cfgRow.gridDim = dim3(NN / LNSR, NB);
    cfgRow.blockDim = dim3(16, LNSR);
    cfgRow.attrs = pdlAttr;
    cfgRow.numAttrs = 1;

    cudaLaunchConfig_t cfgFin = {};
    cfgFin.gridDim = dim3(NN / 16, NB);
    cfgFin.blockDim = dim3(16, 16);
    cfgFin.attrs = pdlAttr;
    cfgFin.numAttrs = 1;

    for (int z = 0; z < NSL - 1; z++) {
        cudaLaunchKernelEx(&cfgCol, k_col);
        cudaLaunchKernelEx(&cfgRow, k_row, obj, crop, idxs, z + 1);
    }
    cudaLaunchKernelEx(&cfgFin, k_final, out);
}

// round 17
// speedup vs baseline: 1.0686x; 1.0686x over previous
#include <cuda_runtime.h>

#define NB   32    // batch
#define PM    4    // probe modes
#define NSL   8    // slices
#define NN  256    // ROI
#define LNS  16    // lines per block
#define LNSR  8    // lines per block for k_row (128 thr)

typedef unsigned long long u64;  // packed complex: lo=re, hi=im (f32x2)

// psi[b][pm][y][x]; state between kernels is Fr(psi) (row-FFT'd, natural order)
__device__ u64 g_psi[NB * PM * NN * NN];
// Hs[row][col] = H[row][col] / 256 (row-major, packed)
__device__ u64 g_Hs[NN * NN];

// ---- packed f32x2 complex primitives (sm_100a) ------------------------------
__device__ __forceinline__ u64 c_pack(float x, float y) {
    u64 r; asm("mov.b64 %0, {%1, %2};" : "=l"(r) : "f"(x), "f"(y)); return r;
}
__device__ __forceinline__ float2 c_unpack(u64 a) {
    float2 r; asm("mov.b64 {%0, %1}, %2;" : "=f"(r.x), "=f"(r.y) : "l"(a)); return r;
}
__device__ __forceinline__ u64 c_add(u64 a, u64 b) {
    u64 r; asm("add.rn.f32x2 %0, %1, %2;" : "=l"(r) : "l"(a), "l"(b)); return r;
}
__device__ __forceinline__ u64 c_sub(u64 a, u64 b) {
    u64 r; asm("sub.rn.f32x2 %0, %1, %2;" : "=l"(r) : "l"(a), "l"(b)); return r;
}
__device__ __forceinline__ u64 c_mi(u64 a) {
    float2 v = c_unpack(a);
    return c_pack(v.y, -v.x);
}
__device__ __forceinline__ u64 cmul_u(u64 a, u64 b) {
    float2 A = c_unpack(a), B = c_unpack(b);
    return c_pack(fmaf(A.x, B.x, -A.y * B.y), fmaf(A.x, B.y, A.y * B.x));
}
template <bool INV>
__device__ __forceinline__ u64 twmul(u64 a, float2 w) {
    float2 A = c_unpack(a);
    float wy = INV ? -w.y : w.y;
    return c_pack(fmaf(A.x, w.x, -A.y * wy), fmaf(A.x, wy, A.y * w.x));
}
__device__ __forceinline__ float2 cmul(float2 a, float2 b) {
    return make_float2(fmaf(a.x, b.x, -a.y * b.y), fmaf(a.x, b.y, a.y * b.x));
}

// W16^m = exp(-2*pi*i*m/16)
__constant__ float2 W16C[10] = {
    { 1.0f,          0.0f        },
    { 0.92387953f,  -0.38268343f },
    { 0.70710678f,  -0.70710678f },
    { 0.38268343f,  -0.92387953f },
    { 0.0f,         -1.0f        },
    {-0.38268343f,  -0.92387953f },
    {-0.70710678f,  -0.70710678f },
    {-0.92387953f,  -0.38268343f },
    {-1.0f,          0.0f        },
    {-0.92387953f,   0.38268343f },
};

template <bool INV>
__device__ __forceinline__ void bf4p(u64& a, u64& b, u64& c, u64& d) {
    u64 t0 = c_add(a, c), t1 = c_sub(a, c);
    u64 t2 = c_add(b, d), t3 = c_sub(b, d);
    a = c_add(t0, t2);
    c = c_sub(t0, t2);
    u64 m = c_mi(t3);
    if (!INV) { b = c_add(t1, m); d = c_sub(t1, m); }
    else      { b = c_sub(t1, m); d = c_add(t1, m); }
}

// 16-point DFT, two-array form (v clobbered; out natural order). The separate
// output array keeps butterflies free of anti-dependencies (max ILP) — the
// in-place folded variant measured SLOWER despite fewer regs (round 16).
template <bool INV>
__device__ __forceinline__ void fft16p(u64* v, u64* out) {
#pragma unroll
    for (int n2 = 0; n2 < 4; n2++)
        bf4p<INV>(v[n2], v[4 + n2], v[8 + n2], v[12 + n2]);
#pragma unroll
    for (int k1 = 1; k1 < 4; k1++)
#pragma unroll
        for (int n2 = 1; n2 < 4; n2++)
            v[4 * k1 + n2] = twmul<INV>(v[4 * k1 + n2], W16C[k1 * n2]);
#pragma unroll
    for (int k1 = 0; k1 < 4; k1++)
        bf4p<INV>(v[4 * k1 + 0], v[4 * k1 + 1], v[4 * k1 + 2], v[4 * k1 + 3]);
#pragma unroll
    for (int k1 = 0; k1 < 4; k1++)
#pragma unroll
        for (int k2 = 0; k2 < 4; k2++)
            out[k1 + 4 * k2] = v[4 * k1 + k2];
}

// tw[k-1] = W256^{j*k}, k=1..15, log-depth product tree.
__device__ __forceinline__ void make_tw256(float2* tw, int j) {
    float s, c;
    sincospif(-(float)j * (1.0f / 128.0f), &s, &c);
    float2 w1 = make_float2(c, s);
    float2 w2 = cmul(w1, w1);
    float2 w3 = cmul(w1, w2);
    float2 w4 = cmul(w2, w2);
    float2 w5 = cmul(w1, w4);
    float2 w6 = cmul(w2, w4);
    float2 w7 = cmul(w3, w4);
    float2 w8 = cmul(w4, w4);
    tw[0] = w1;  tw[1] = w2;  tw[2] = w3;  tw[3] = w4;
    tw[4] = w5;  tw[5] = w6;  tw[6] = w7;  tw[7] = w8;
    tw[8]  = cmul(w1, w8);
    tw[9]  = cmul(w2, w8);
    tw[10] = cmul(w3, w8);
    tw[11] = cmul(w4, w8);
    tw[12] = cmul(w5, w8);
    tw[13] = cmul(w6, w8);
    tw[14] = cmul(w7, w8);
}

// Warp-local 256-pt FFT (16 threads/line in one warp).
template <bool INV>
__device__ __forceinline__ void fft256p(u64 reg[16], int t, u64* tr,
                                        const float2* tw) {
    u64 A[16];
    fft16p<INV>(reg, A);
#pragma unroll
    for (int k1 = 1; k1 < 16; k1++)
        A[k1] = twmul<INV>(A[k1], tw[k1 - 1]);
#pragma unroll
    for (int k1 = 0; k1 < 16; k1++) tr[k1 * 17 + t] = A[k1];
    __syncwarp();
    u64 B[16];
#pragma unroll
    for (int n2 = 0; n2 < 16; n2++) B[n2] = tr[t * 17 + n2];
    __syncwarp();
    fft16p<INV>(B, reg);
}

// Cross-warp 256-pt FFT (thread owns a column; j spans warps).
template <bool INV>
__device__ __forceinline__ void fft256blk(u64 reg[16], int j, int ln, u64* W,
                                          const float2* tw) {
    u64 A[16];
    fft16p<INV>(reg, A);
#pragma unroll
    for (int k1 = 1; k1 < 16; k1++)
        A[k1] = twmul<INV>(A[k1], tw[k1 - 1]);
#pragma unroll
    for (int k1 = 0; k1 < 16; k1++) W[(k1 * 17 + j) * 16 + ln] = A[k1];
    __syncthreads();
    u64 B[16];
#pragma unroll
    for (int n2 = 0; n2 < 16; n2++) B[n2] = W[(j * 17 + n2) * 16 + ln];
    __syncthreads();
    fft16p<INV>(B, reg);
}

// ---------------------------------------------------------------------------
__global__ void k_prep(const float* __restrict__ Hr, const float* __restrict__ Hi) {
    int i = blockIdx.x * blockDim.x + threadIdx.x;
    g_Hs[i] = c_pack(Hr[i] * (1.0f / 256.0f), Hi[i] * (1.0f / 256.0f));
}

// ---------------------------------------------------------------------------
// k_init: psi = probe_translated * obj0, then forward row FFT. Warp-sync.
// ---------------------------------------------------------------------------
__global__ __launch_bounds__(256, 2) void k_init(
    const float* __restrict__ obj, const float* __restrict__ probe,
    const float* __restrict__ shifts, const int* __restrict__ crop,
    const int* __restrict__ idxs) {
    __shared__ u64 buf[LNS * 272];
    int t = threadIdx.x, ly = threadIdx.y;
    int img = blockIdx.y;
    int b = img >> 2, pm = img & 3;
    int r = blockIdx.x * LNS + ly;

    int id = idxs[b];
    float tH = shifts[2 * id + 0];
    float tW = shifts[2 * id + 1];
    int p0 = crop[2 * id + 0];
    int p1 = crop[2 * id + 1];

    float ys = (float)r - tH;
    float y0f = floorf(ys);
    float wy = ys - y0f;
    int y0 = (int)y0f;

    u64 reg[16];
#pragma unroll
    for (int jj = 0; jj < 16; jj++) {
        int c = 16 * jj + t;
        float xs = (float)c - tW;
        float x0f = floorf(xs);
        float wx = xs - x0f;
        int x0 = (int)x0f;

        float amp = 0.f, ph = 0.f;
#pragma unroll
        for (int dy = 0; dy < 2; dy++) {
            int yy = y0 + dy;
            float wyt = dy ? wy : (1.f - wy);
            if (yy >= 0 && yy < NN) {
#pragma unroll
                for (int dx = 0; dx < 2; dx++) {
                    int xx = x0 + dx;
                    float w = wyt * (dx ? wx : (1.f - wx));
                    if (xx >= 0 && xx < NN) {
                        float2 v = *(const float2*)(probe +
                            ((size_t)(pm * NN + yy) * NN + xx) * 2);
                        amp = fmaf(w, v.x, amp);
                        ph  = fmaf(w, v.y, ph);
                    }
                }
            }
        }
        float sn, cs;
        __sincosf(ph, &sn, &cs);
        float2 pc = make_float2(amp * cs, amp * sn);

        float2 o = *(const float2*)(obj + (((size_t)(p0 + r)) * 1024 + (p1 + c)) * 2);
        float so, co;
        __sincosf(o.y, &so, &co);
        float2 oc = make_float2(o.x * co, o.x * so);
        reg[jj] = c_pack(fmaf(pc.x, oc.x, -pc.y * oc.y),
                         fmaf(pc.x, oc.y,  pc.y * oc.x));
    }

    float2 tw[15];
    make_tw256(tw, t);
    fft256p<false>(reg, t, buf + ly * 272, tw);

    u64* dst = g_psi + ((size_t)img * NN + r) * NN;
#pragma unroll
    for (int k = 0; k < 16; k++) dst[16 * k + t] = reg[k];
}

// ---------------------------------------------------------------------------
// k_col: per column: Fc -> * (H/256) -> Fc^{-1}. PDL prologue; no staging.
// (256,3): 3 resident blocks (85-reg cap; body measured ~80 regs) — 50% more
// warps to fill the block-barrier bubbles inside fft256blk.
// ---------------------------------------------------------------------------
__global__ __launch_bounds__(256, 3) void k_col() {
    __shared__ u64 W[16 * 17 * 16];
    int t = threadIdx.x;   // column within tile (line)
    int j = threadIdx.y;   // intra-line FFT index
    int img = blockIdx.y;
    int cb = blockIdx.x * 16;
    u64* psi = g_psi + (size_t)img * NN * NN;

    float2 tw[15];
    make_tw256(tw, j);      // psi-independent prologue

    cudaGridDependencySynchronize();

    u64 reg[16];
#pragma unroll
    for (int it = 0; it < 16; it++)
        reg[it] = psi[(size_t)(16 * it + j) * NN + cb + t];

    fft256blk<false>(reg, j, t, W, tw);

#pragma unroll
    for (int k = 0; k < 16; k++)
        reg[k] = cmul_u(reg[k], g_Hs[(size_t)(16 * k + j) * NN + cb + t]);

    fft256blk<true>(reg, j, t, W, tw);

#pragma unroll
    for (int k = 0; k < 16; k++)
        psi[(size_t)(16 * k + j) * NN + cb + t] = reg[k];
}

// ---------------------------------------------------------------------------
// k_row: per row: Fr^{-1}/256 -> * obj_z -> Fr. 8 lines / 128 threads.
// PDL: obj sincos + twiddle prologue overlaps predecessor's tail wave.
// ---------------------------------------------------------------------------
__global__ __launch_bounds__(128, 4) void k_row(
    const float* __restrict__ obj, const int* __restrict__ crop,
    const int* __restrict__ idxs, int z) {
    __shared__ u64 buf[LNSR * 272];
    __shared__ u64 sOC[LNSR * 256];
    int t = threadIdx.x, ly = threadIdx.y;
    int b = blockIdx.y;
    int r = blockIdx.x * LNSR + ly;

    int id = idxs[b];
    int p0 = crop[2 * id + 0];
    int p1 = crop[2 * id + 1];
    const float inv = 1.0f / 256.0f;

    u64* oc = sOC + ly * 256;
#pragma unroll
    for (int jj = 0; jj < 16; jj++) {
        int c = 16 * jj + t;
        float2 o = *(const float2*)(obj +
            (((size_t)z * 1024 + p0 + r) * 1024 + (p1 + c)) * 2);
        float so, co;
        __sincosf(o.y, &so, &co);
        oc[c] = c_pack(o.x * co * inv, o.x * so * inv);
    }
    __syncwarp();

    float2 tw[15];
    make_tw256(tw, t);

    cudaGridDependencySynchronize();

    for (int pm = 0; pm < PM; pm++) {
        u64* psi = g_psi + ((size_t)(b * PM + pm) * NN + r) * NN;
        u64 reg[16];
#pragma unroll
        for (int k = 0; k < 16; k++) reg[k] = psi[16 * k + t];

        fft256p<true>(reg, t, buf + ly * 272, tw);
#pragma unroll
        for (int jj = 0; jj < 16; jj++) reg[jj] = cmul_u(reg[jj], oc[16 * jj + t]);
        fft256p<false>(reg, t, buf + ly * 272, tw);

#pragma unroll
        for (int k = 0; k < 16; k++) psi[16 * k + t] = reg[k];
    }
}

// ---------------------------------------------------------------------------
// k_final: per column: Fc, accumulate |.|^2 over 4 probe modes. PDL prologue.
// (256,3) like k_col.
// ---------------------------------------------------------------------------
__global__ __launch_bounds__(256, 3) void k_final(float* __restrict__ out) {
    __shared__ u64 W[16 * 17 * 16];
    int t = threadIdx.x;
    int j = threadIdx.y;
    int b = blockIdx.y;
    int cb = blockIdx.x * 16;

    float2 tw[15];
    make_tw256(tw, j);

    cudaGridDependencySynchronize();

    float acc[16];
#pragma unroll
    for (int k = 0; k < 16; k++) acc[k] = 0.f;

    for (int pm = 0; pm < PM; pm++) {
        u64* psi = g_psi + (size_t)(b * PM + pm) * NN * NN;
        u64 reg[16];
#pragma unroll
        for (int it = 0; it < 16; it++)
            reg[it] = psi[(size_t)(16 * it + j) * NN + cb + t];

        fft256blk<false>(reg, j, t, W, tw);

#pragma unroll
        for (int k = 0; k < 16; k++) {
            float2 v = c_unpack(reg[k]);
            acc[k] = fmaf(v.x, v.x, fmaf(v.y, v.y, acc[k]));
        }
    }

#pragma unroll
    for (int k = 0; k < 16; k++)
        out[(size_t)b * NN * NN + (size_t)(16 * k + j) * NN + cb + t] = acc[k];
}

// ---------------------------------------------------------------------------
extern "C" void kernel_launch(void* const* d_in, const int* in_sizes, int n_in,
                              void* d_out, int out_size) {
    const float* obj    = (const float*)d_in[0];  // (1,8,1024,1024,2)
    const float* probe  = (const float*)d_in[1];  // (4,256,256,2)
    const float* shifts = (const float*)d_in[2];  // (1024,2)
    const int*   crop   = (const int*)d_in[3];    // (1024,2)
    const float* Hr     = (const float*)d_in[4];  // (256,256)
    const float* Hi     = (const float*)d_in[5];  // (256,256)
    const int*   idxs   = (const int*)d_in[6];    // (32,)
    float* out = (float*)d_out;                   // (32,256,256)

    cudaLaunchAttribute pdlAttr[1];
    pdlAttr[0].id = cudaLaunchAttributeProgrammaticStreamSerialization;
    pdlAttr[0].val.programmaticStreamSerializationAllowed = 1;

    k_prep<<<256, 256>>>(Hr, Hi);
    k_init<<<dim3(NN / LNS, NB * PM), dim3(16, LNS)>>>(obj, probe, shifts, crop, idxs);

    cudaLaunchConfig_t cfgCol = {};
    cfgCol.gridDim = dim3(NN / 16, NB * PM);
    cfgCol.blockDim = dim3(16, 16);
    cfgCol.attrs = pdlAttr;
    cfgCol.numAttrs = 1;

    cudaLaunchConfig_t cfgRow = {};
    cfgRow.gridDim = dim3(NN / LNSR, NB);
    cfgRow.blockDim = dim3(16, LNSR);
    cfgRow.attrs = pdlAttr;
    cfgRow.numAttrs = 1;

    cudaLaunchConfig_t cfgFin = {};
    cfgFin.gridDim = dim3(NN / 16, NB);
    cfgFin.blockDim = dim3(16, 16);
    cfgFin.attrs = pdlAttr;
    cfgFin.numAttrs = 1;

    for (int z = 0; z < NSL - 1; z++) {
        cudaLaunchKernelEx(&cfgCol, k_col);
        cudaLaunchKernelEx(&cfgRow, k_row, obj, crop, idxs, z + 1);
    }
    cudaLaunchKernelEx(&cfgFin, k_final, out);
}